// round 4
// baseline (speedup 1.0000x reference)
#include <cuda_runtime.h>
#include <cuda_bf16.h>

#define NBX 512
#define NBY 512
#define BSX_F 1.953125f           /* 1000/512, exact in fp32 */
#define INV_BSX_F 0.512f          /* 512/1000 */
#define NBINS (NBX * NBY)

// Scale = 1/(BSX*BSY*CAP); CAP_H == CAP_V == 0.1 so one scale serves both maps.
__device__ __constant__ float d_scale = (float)(1.0 / (1.953125 * 1.953125 * 0.1));

// Interleaved difference plane: .x = h-weighted, .y = v-weighted. 2 MB, L2-resident.
__device__ __align__(8) float2 g_d[NBINS];

__global__ void zero_planes() {
    int i = blockIdx.x * blockDim.x + threadIdx.x;
    if (i < NBINS) g_d[i] = make_float2(0.0f, 0.0f);
}

// f(i) = clip(min(hi_v, e[i+1]) - max(lo_v, e[i]), 0, BSX) -- reference formula verbatim.
__device__ __forceinline__ float overlap_f(float lo_v, float hi_v, int i) {
    float lo = fmaxf(lo_v, (float)i * BSX_F);
    float hi = fminf(hi_v, (float)(i + 1) * BSX_F);
    return fminf(fmaxf(hi - lo, 0.0f), BSX_F);
}

// Exact bin index: floor(v / BSX) with fixup against exact fp32 edges.
__device__ __forceinline__ int bin_of(float v) {
    int i = (int)(v * INV_BSX_F);
    if (v < (float)i * BSX_F) i--;
    else if (v >= (float)(i + 1) * BSX_F) i++;
    return i;
}

// Change-points of f along one axis: at most 4 nonzero first differences.
__device__ __forceinline__ int build_diffs(float lo_v, float hi_v, int* idx, float* df) {
    int i0 = bin_of(lo_v);
    int i1 = bin_of(hi_v);
    int cand[4]; int nc = 0;
    cand[nc++] = i0;
    cand[nc++] = i0 + 1;
    if (i1 > i0) {
        if (i1 > i0 + 1) cand[nc++] = i1;
        cand[nc++] = i1 + 1;
    }
    int n = 0;
    #pragma unroll
    for (int k = 0; k < 4; k++) {
        if (k >= nc) break;
        int i = cand[k];
        if (i < 0 || i >= NBX) continue;
        float fprev = (i > 0) ? overlap_f(lo_v, hi_v, i - 1) : 0.0f;
        float d = overlap_f(lo_v, hi_v, i) - fprev;
        if (d != 0.0f) { idx[n] = i; df[n] = d; n++; }
    }
    return n;
}

__global__ void scatter_kernel(const float* __restrict__ pin_pos,
                               const float* __restrict__ net_weights,
                               const int*   __restrict__ netpin_start,
                               const int*   __restrict__ flat_netpin,
                               int num_nets, int P) {
    int n = blockIdx.x * blockDim.x + threadIdx.x;
    if (n >= num_nets) return;
    int s = netpin_start[n];
    int e = netpin_start[n + 1];

    float xmin = 3.0e38f, xmax = -3.0e38f, ymin = 3.0e38f, ymax = -3.0e38f;
    for (int p = s; p < e; p++) {
        int pi = flat_netpin[p];
        float x = __ldg(&pin_pos[pi]);
        float y = __ldg(&pin_pos[P + pi]);
        xmin = fminf(xmin, x); xmax = fmaxf(xmax, x);
        ymin = fminf(ymin, y); ymax = fmaxf(ymax, y);
    }

    float w  = net_weights[n];
    float dx = xmax - xmin;
    float dy = ymax - ymin;
    float wh = (dy > 0.0f) ? (w / dy) : 0.0f;   // horizontal map weight
    float wv = (dx > 0.0f) ? (w / dx) : 0.0f;   // vertical map weight

    int   ix[4], iy[4];
    float dfx[4], dfy[4];
    int nx = build_diffs(xmin, xmax, ix, dfx);
    int ny = build_diffs(ymin, ymax, iy, dfy);

    for (int a = 0; a < nx; a++) {
        int rowbase = ix[a] * NBY;
        float fh = dfx[a] * wh;
        float fv = dfx[a] * wv;
        for (int b = 0; b < ny; b++) {
            float g = dfy[b];
            atomicAdd(&g_d[rowbase + iy[b]], make_float2(fh * g, fv * g));
        }
    }
}

// Inclusive scan along j (fast axis) for each row, both planes at once.
// grid = NBX, block = 512.
__global__ void row_scan_kernel() {
    int row = blockIdx.x;
    int tid = threadIdx.x;
    int lane = tid & 31;
    int wid  = tid >> 5;

    float2 v = g_d[row * NBY + tid];
    #pragma unroll
    for (int off = 1; off < 32; off <<= 1) {
        float tx = __shfl_up_sync(0xFFFFFFFFu, v.x, off);
        float ty = __shfl_up_sync(0xFFFFFFFFu, v.y, off);
        if (lane >= off) { v.x += tx; v.y += ty; }
    }
    __shared__ float2 wsum[16];
    if (lane == 31) wsum[wid] = v;
    __syncthreads();
    if (wid == 0) {
        float2 t = (lane < 16) ? wsum[lane] : make_float2(0.0f, 0.0f);
        #pragma unroll
        for (int off = 1; off < 16; off <<= 1) {
            float ux = __shfl_up_sync(0xFFFFFFFFu, t.x, off);
            float uy = __shfl_up_sync(0xFFFFFFFFu, t.y, off);
            if (lane >= off) { t.x += ux; t.y += uy; }
        }
        if (lane < 16) wsum[lane] = t;
    }
    __syncthreads();
    if (wid > 0) { v.x += wsum[wid - 1].x; v.y += wsum[wid - 1].y; }
    g_d[row * NBY + tid] = v;
}

// Column scan (along i) + finalize. One thread per column; coalesced float2 loads.
__global__ void col_scan_finalize_kernel(float* __restrict__ out) {
    int j = blockIdx.x * blockDim.x + threadIdx.x;
    if (j >= NBY) return;
    float sh = 0.0f, sv = 0.0f;
    float sc = d_scale;
    #pragma unroll 8
    for (int i = 0; i < NBX; i++) {
        int id = i * NBY + j;
        float2 d = g_d[id];
        sh += d.x;
        sv += d.y;
        out[id] = fmaxf(fabsf(sh * sc), fabsf(sv * sc));
    }
}

extern "C" void kernel_launch(void* const* d_in, const int* in_sizes, int n_in,
                              void* d_out, int out_size) {
    const float* pin_pos      = (const float*)d_in[0];
    const float* net_weights  = (const float*)d_in[1];
    const int*   netpin_start = (const int*)  d_in[2];
    const int*   flat_netpin  = (const int*)  d_in[3];
    float* out = (float*)d_out;

    int num_nets = in_sizes[2] - 1;
    int P        = in_sizes[0] / 2;

    zero_planes<<<(NBINS + 255) / 256, 256>>>();
    scatter_kernel<<<(num_nets + 255) / 256, 256>>>(pin_pos, net_weights,
                                                    netpin_start, flat_netpin,
                                                    num_nets, P);
    row_scan_kernel<<<NBX, NBY>>>();
    col_scan_finalize_kernel<<<(NBY + 255) / 256, 256>>>(out);
}

// round 8
// speedup vs baseline: 1.5581x; 1.5581x over previous
#include <cuda_runtime.h>
#include <cuda_bf16.h>

#define NBX 512
#define NBY 512
#define BSX_F 1.953125f           /* 1000/512, exact in fp32 */
#define INV_BSX_F 0.512f          /* 512/1000 */
#define NBINS (NBX * NBY)

#define NTILES 64
#define ROWS_PER_TILE 8           /* NBX / NTILES */

// Scale = 1/(BSX*BSY*CAP); CAP_H == CAP_V == 0.1 so one scale serves both maps.
__device__ __constant__ float d_scale = (float)(1.0 / (1.953125 * 1.953125 * 0.1));

// Interleaved difference plane: .x = h-weighted, .y = v-weighted. 2 MB, L2-resident.
__device__ __align__(8) float2 g_d[NBINS];
// Per-(tile, column) partial sums for the column scan.
__device__ __align__(8) float2 g_part[NTILES * NBY];

__global__ void zero_planes() {
    int i = blockIdx.x * blockDim.x + threadIdx.x;
    if (i < NBINS) g_d[i] = make_float2(0.0f, 0.0f);
}

// f(i) = clip(min(hi_v, e[i+1]) - max(lo_v, e[i]), 0, BSX) -- reference formula verbatim.
__device__ __forceinline__ float overlap_f(float lo_v, float hi_v, int i) {
    float lo = fmaxf(lo_v, (float)i * BSX_F);
    float hi = fminf(hi_v, (float)(i + 1) * BSX_F);
    return fminf(fmaxf(hi - lo, 0.0f), BSX_F);
}

// Exact bin index: floor(v / BSX) with fixup against exact fp32 edges.
__device__ __forceinline__ int bin_of(float v) {
    int i = (int)(v * INV_BSX_F);
    if (v < (float)i * BSX_F) i--;
    else if (v >= (float)(i + 1) * BSX_F) i++;
    return i;
}

// Change-points of f along one axis: at most 4 nonzero first differences.
__device__ __forceinline__ int build_diffs(float lo_v, float hi_v, int* idx, float* df) {
    int i0 = bin_of(lo_v);
    int i1 = bin_of(hi_v);
    int cand[4]; int nc = 0;
    cand[nc++] = i0;
    cand[nc++] = i0 + 1;
    if (i1 > i0) {
        if (i1 > i0 + 1) cand[nc++] = i1;
        cand[nc++] = i1 + 1;
    }
    int n = 0;
    #pragma unroll
    for (int k = 0; k < 4; k++) {
        if (k >= nc) break;
        int i = cand[k];
        if (i < 0 || i >= NBX) continue;
        float fprev = (i > 0) ? overlap_f(lo_v, hi_v, i - 1) : 0.0f;
        float d = overlap_f(lo_v, hi_v, i) - fprev;
        if (d != 0.0f) { idx[n] = i; df[n] = d; n++; }
    }
    return n;
}

__global__ void scatter_kernel(const float* __restrict__ pin_pos,
                               const float* __restrict__ net_weights,
                               const int*   __restrict__ netpin_start,
                               const int*   __restrict__ flat_netpin,
                               int num_nets, int P) {
    int n = blockIdx.x * blockDim.x + threadIdx.x;
    if (n >= num_nets) return;
    int s = netpin_start[n];
    int e = netpin_start[n + 1];

    float xmin = 3.0e38f, xmax = -3.0e38f, ymin = 3.0e38f, ymax = -3.0e38f;
    for (int p = s; p < e; p++) {
        int pi = flat_netpin[p];
        float x = __ldg(&pin_pos[pi]);
        float y = __ldg(&pin_pos[P + pi]);
        xmin = fminf(xmin, x); xmax = fmaxf(xmax, x);
        ymin = fminf(ymin, y); ymax = fmaxf(ymax, y);
    }

    float w  = net_weights[n];
    float dx = xmax - xmin;
    float dy = ymax - ymin;
    float wh = (dy > 0.0f) ? (w / dy) : 0.0f;   // horizontal map weight
    float wv = (dx > 0.0f) ? (w / dx) : 0.0f;   // vertical map weight

    int   ix[4], iy[4];
    float dfx[4], dfy[4];
    int nx = build_diffs(xmin, xmax, ix, dfx);
    int ny = build_diffs(ymin, ymax, iy, dfy);

    for (int a = 0; a < nx; a++) {
        int rowbase = ix[a] * NBY;
        float fh = dfx[a] * wh;
        float fv = dfx[a] * wv;
        for (int b = 0; b < ny; b++) {
            float g = dfy[b];
            atomicAdd(&g_d[rowbase + iy[b]], make_float2(fh * g, fv * g));
        }
    }
}

// Inclusive scan along j (fast axis) for each row, both planes at once.
// grid = NBX, block = 512.
__global__ void row_scan_kernel() {
    int row = blockIdx.x;
    int tid = threadIdx.x;
    int lane = tid & 31;
    int wid  = tid >> 5;

    float2 v = g_d[row * NBY + tid];
    #pragma unroll
    for (int off = 1; off < 32; off <<= 1) {
        float tx = __shfl_up_sync(0xFFFFFFFFu, v.x, off);
        float ty = __shfl_up_sync(0xFFFFFFFFu, v.y, off);
        if (lane >= off) { v.x += tx; v.y += ty; }
    }
    __shared__ float2 wsum[16];
    if (lane == 31) wsum[wid] = v;
    __syncthreads();
    if (wid == 0) {
        float2 t = (lane < 16) ? wsum[lane] : make_float2(0.0f, 0.0f);
        #pragma unroll
        for (int off = 1; off < 16; off <<= 1) {
            float ux = __shfl_up_sync(0xFFFFFFFFu, t.x, off);
            float uy = __shfl_up_sync(0xFFFFFFFFu, t.y, off);
            if (lane >= off) { t.x += ux; t.y += uy; }
        }
        if (lane < 16) wsum[lane] = t;
    }
    __syncthreads();
    if (wid > 0) { v.x += wsum[wid - 1].x; v.y += wsum[wid - 1].y; }
    g_d[row * NBY + tid] = v;
}

// ── Column scan, phase 1: per-tile partial sums.
// grid = (NBY/256, NTILES), block = 256. Thread = one column within one row-tile.
__global__ void col_partial_kernel() {
    int j = blockIdx.x * blockDim.x + threadIdx.x;
    int t = blockIdx.y;
    int base = t * ROWS_PER_TILE * NBY + j;
    float sh = 0.0f, sv = 0.0f;
    #pragma unroll
    for (int r = 0; r < ROWS_PER_TILE; r++) {
        float2 d = g_d[base + r * NBY];
        sh += d.x;
        sv += d.y;
    }
    g_part[t * NBY + j] = make_float2(sh, sv);
}

// ── Column scan, phase 2: redundant exclusive prefix over preceding tiles +
// in-tile running sums + finalize. grid = (NBY/256, NTILES), block = 256.
// Each thread sums the partials of tiles [0, t) for its column (ascending order
// -> identical numerics to a serial column scan), then finishes its 8 rows.
__global__ void col_finalize_kernel(float* __restrict__ out) {
    int j = blockIdx.x * blockDim.x + threadIdx.x;
    int t = blockIdx.y;
    float sh = 0.0f, sv = 0.0f;
    for (int tp = 0; tp < t; tp++) {
        float2 p = g_part[tp * NBY + j];
        sh += p.x;
        sv += p.y;
    }
    float sc = d_scale;
    int base = t * ROWS_PER_TILE * NBY + j;
    #pragma unroll
    for (int r = 0; r < ROWS_PER_TILE; r++) {
        float2 d = g_d[base + r * NBY];
        sh += d.x;
        sv += d.y;
        out[base + r * NBY] = fmaxf(fabsf(sh * sc), fabsf(sv * sc));
    }
}

extern "C" void kernel_launch(void* const* d_in, const int* in_sizes, int n_in,
                              void* d_out, int out_size) {
    const float* pin_pos      = (const float*)d_in[0];
    const float* net_weights  = (const float*)d_in[1];
    const int*   netpin_start = (const int*)  d_in[2];
    const int*   flat_netpin  = (const int*)  d_in[3];
    float* out = (float*)d_out;

    int num_nets = in_sizes[2] - 1;
    int P        = in_sizes[0] / 2;

    zero_planes<<<(NBINS + 255) / 256, 256>>>();
    scatter_kernel<<<(num_nets + 255) / 256, 256>>>(pin_pos, net_weights,
                                                    netpin_start, flat_netpin,
                                                    num_nets, P);
    row_scan_kernel<<<NBX, NBY>>>();
    col_partial_kernel<<<dim3(NBY / 256, NTILES), 256>>>();
    col_finalize_kernel<<<dim3(NBY / 256, NTILES), 256>>>(out);
}

// round 9
// speedup vs baseline: 1.6469x; 1.0570x over previous
#include <cuda_runtime.h>
#include <cuda_bf16.h>

#define NBX 512
#define NBY 512
#define BSX_F 1.953125f           /* 1000/512, exact in fp32 */
#define INV_BSX_F 0.512f          /* 512/1000 */
#define NBINS (NBX * NBY)

#define NTILES 64
#define ROWS_PER_TILE 8           /* NBX / NTILES */
#define NPART (NTILES * NBY)

// Scale = 1/(BSX*BSY*CAP); CAP_H == CAP_V == 0.1 so one scale serves both maps.
__device__ __constant__ float d_scale = (float)(1.0 / (1.953125 * 1.953125 * 0.1));

// Interleaved difference plane: .x = h-weighted, .y = v-weighted. 2 MB, L2-resident.
__device__ __align__(16) float2 g_d[NBINS];
// Per-(tile, column) partial sums for the column scan (accumulated atomically).
__device__ __align__(16) float2 g_part[NPART];

// Zero both scratch planes with vectorized stores. grid covers NBINS/2 float4s.
__global__ void zero_planes() {
    int i = blockIdx.x * blockDim.x + threadIdx.x;
    float4 z = make_float4(0.0f, 0.0f, 0.0f, 0.0f);
    if (i < NBINS / 2)  reinterpret_cast<float4*>(g_d)[i] = z;
    if (i < NPART / 2)  reinterpret_cast<float4*>(g_part)[i] = z;
}

// f(i) = clip(min(hi_v, e[i+1]) - max(lo_v, e[i]), 0, BSX) -- reference formula verbatim.
__device__ __forceinline__ float overlap_f(float lo_v, float hi_v, int i) {
    float lo = fmaxf(lo_v, (float)i * BSX_F);
    float hi = fminf(hi_v, (float)(i + 1) * BSX_F);
    return fminf(fmaxf(hi - lo, 0.0f), BSX_F);
}

// Exact bin index: floor(v / BSX) with fixup against exact fp32 edges.
__device__ __forceinline__ int bin_of(float v) {
    int i = (int)(v * INV_BSX_F);
    if (v < (float)i * BSX_F) i--;
    else if (v >= (float)(i + 1) * BSX_F) i++;
    return i;
}

// Change-points of f along one axis: at most 4 nonzero first differences.
__device__ __forceinline__ int build_diffs(float lo_v, float hi_v, int* idx, float* df) {
    int i0 = bin_of(lo_v);
    int i1 = bin_of(hi_v);
    int cand[4]; int nc = 0;
    cand[nc++] = i0;
    cand[nc++] = i0 + 1;
    if (i1 > i0) {
        if (i1 > i0 + 1) cand[nc++] = i1;
        cand[nc++] = i1 + 1;
    }
    int n = 0;
    #pragma unroll
    for (int k = 0; k < 4; k++) {
        if (k >= nc) break;
        int i = cand[k];
        if (i < 0 || i >= NBX) continue;
        float fprev = (i > 0) ? overlap_f(lo_v, hi_v, i - 1) : 0.0f;
        float d = overlap_f(lo_v, hi_v, i) - fprev;
        if (d != 0.0f) { idx[n] = i; df[n] = d; n++; }
    }
    return n;
}

__global__ void scatter_kernel(const float* __restrict__ pin_pos,
                               const float* __restrict__ net_weights,
                               const int*   __restrict__ netpin_start,
                               const int*   __restrict__ flat_netpin,
                               int num_nets, int P) {
    int n = blockIdx.x * blockDim.x + threadIdx.x;
    if (n >= num_nets) return;
    int s = netpin_start[n];
    int e = netpin_start[n + 1];

    float xmin = 3.0e38f, xmax = -3.0e38f, ymin = 3.0e38f, ymax = -3.0e38f;
    for (int p = s; p < e; p++) {
        int pi = flat_netpin[p];
        float x = __ldg(&pin_pos[pi]);
        float y = __ldg(&pin_pos[P + pi]);
        xmin = fminf(xmin, x); xmax = fmaxf(xmax, x);
        ymin = fminf(ymin, y); ymax = fmaxf(ymax, y);
    }

    float w  = net_weights[n];
    float dx = xmax - xmin;
    float dy = ymax - ymin;
    float wh = (dy > 0.0f) ? (w / dy) : 0.0f;   // horizontal map weight
    float wv = (dx > 0.0f) ? (w / dx) : 0.0f;   // vertical map weight

    int   ix[4], iy[4];
    float dfx[4], dfy[4];
    int nx = build_diffs(xmin, xmax, ix, dfx);
    int ny = build_diffs(ymin, ymax, iy, dfy);

    for (int a = 0; a < nx; a++) {
        int rowbase = ix[a] * NBY;
        float fh = dfx[a] * wh;
        float fv = dfx[a] * wv;
        for (int b = 0; b < ny; b++) {
            float g = dfy[b];
            atomicAdd(&g_d[rowbase + iy[b]], make_float2(fh * g, fv * g));
        }
    }
}

// Inclusive scan along j (fast axis) for each row, both planes at once.
// Each thread then atomically folds its final scanned value into its tile's
// column partial -- this replaces the former col_partial kernel.
// grid = NBX, block = 512.
__global__ void row_scan_kernel() {
    int row = blockIdx.x;
    int tid = threadIdx.x;
    int lane = tid & 31;
    int wid  = tid >> 5;

    float2 v = g_d[row * NBY + tid];
    #pragma unroll
    for (int off = 1; off < 32; off <<= 1) {
        float tx = __shfl_up_sync(0xFFFFFFFFu, v.x, off);
        float ty = __shfl_up_sync(0xFFFFFFFFu, v.y, off);
        if (lane >= off) { v.x += tx; v.y += ty; }
    }
    __shared__ float2 wsum[16];
    if (lane == 31) wsum[wid] = v;
    __syncthreads();
    if (wid == 0) {
        float2 t = (lane < 16) ? wsum[lane] : make_float2(0.0f, 0.0f);
        #pragma unroll
        for (int off = 1; off < 16; off <<= 1) {
            float ux = __shfl_up_sync(0xFFFFFFFFu, t.x, off);
            float uy = __shfl_up_sync(0xFFFFFFFFu, t.y, off);
            if (lane >= off) { t.x += ux; t.y += uy; }
        }
        if (lane < 16) wsum[lane] = t;
    }
    __syncthreads();
    if (wid > 0) { v.x += wsum[wid - 1].x; v.y += wsum[wid - 1].y; }
    g_d[row * NBY + tid] = v;

    int t = row >> 3;   /* row / ROWS_PER_TILE */
    atomicAdd(&g_part[t * NBY + tid], v);
}

// Column finalize: redundant exclusive prefix over preceding tiles' partials +
// in-tile running sums + output. grid = (NBY/256, NTILES), block = 256.
__global__ void col_finalize_kernel(float* __restrict__ out) {
    int j = blockIdx.x * blockDim.x + threadIdx.x;
    int t = blockIdx.y;
    float sh = 0.0f, sv = 0.0f;
    for (int tp = 0; tp < t; tp++) {
        float2 p = g_part[tp * NBY + j];
        sh += p.x;
        sv += p.y;
    }
    float sc = d_scale;
    int base = t * ROWS_PER_TILE * NBY + j;
    #pragma unroll
    for (int r = 0; r < ROWS_PER_TILE; r++) {
        float2 d = g_d[base + r * NBY];
        sh += d.x;
        sv += d.y;
        out[base + r * NBY] = fmaxf(fabsf(sh * sc), fabsf(sv * sc));
    }
}

extern "C" void kernel_launch(void* const* d_in, const int* in_sizes, int n_in,
                              void* d_out, int out_size) {
    const float* pin_pos      = (const float*)d_in[0];
    const float* net_weights  = (const float*)d_in[1];
    const int*   netpin_start = (const int*)  d_in[2];
    const int*   flat_netpin  = (const int*)  d_in[3];
    float* out = (float*)d_out;

    int num_nets = in_sizes[2] - 1;
    int P        = in_sizes[0] / 2;

    zero_planes<<<(NBINS / 2 + 255) / 256, 256>>>();
    scatter_kernel<<<(num_nets + 255) / 256, 256>>>(pin_pos, net_weights,
                                                    netpin_start, flat_netpin,
                                                    num_nets, P);
    row_scan_kernel<<<NBX, NBY>>>();
    col_finalize_kernel<<<dim3(NBY / 256, NTILES), 256>>>(out);
}